// round 16
// baseline (speedup 1.0000x reference)
#include <cuda_runtime.h>
#include <cuda_fp16.h>
#include <mma.h>
#include <math.h>
#include <stdint.h>

using namespace nvcuda;

#define BATCH 8192
#define DIN   1024
#define DZ    256
#define DH    256
#define DT    16
#define DREC  256

// tiled fp16 layout:
//   activation tile: 128 rows x 40-half pitch (cols 0..31 valid) = 5120 halves
//   weight tile:      64 rows x 40-half pitch                    = 2560 halves

// ---------------- scratch (device globals) ----------------------------------
__device__ float g_mu_q   [BATCH * DZ];
__device__ float g_sigma_q[BATCH * DZ];
__device__ float g_sigma_p[BATCH * DZ];
__device__ float g_mu_p   [BATCH * DZ];
__device__ float g_ti     [BATCH * DT];
__device__ float g_theta  [BATCH * DT];
__device__ double g_acc[3];

__device__ __align__(16) half g_It [64 * 32 * 5120];
__device__ __align__(16) half g_h  [64 * 8 * 5120];
__device__ __align__(16) half g_zm [64 * 8 * 5120];
__device__ __align__(16) half g_z  [64 * 8 * 5120];
__device__ __align__(16) half g_sp [64 * 8 * 5120];
__device__ __align__(16) half g_r1 [64 * 8 * 5120];
__device__ __align__(16) half g_Wpmu [4 * 32 * 2560];
__device__ __align__(16) half g_Wplv [4 * 32 * 2560];
__device__ __align__(16) half g_Wz2h [4 * 8 * 2560];
__device__ __align__(16) half g_Wh2h [4 * 8 * 2560];
__device__ __align__(16) half g_Wprmu[4 * 8 * 2560];
__device__ __align__(16) half g_Wprlv[4 * 8 * 2560];
__device__ __align__(16) half g_Wi2t [1 * 32 * 2560];   // rows 16..63 garbage (cols discarded)
__device__ __align__(16) half g_Wv   [1 * 8 * 2560];    // relu applied; rows 16..63 garbage
__device__ __align__(16) half g_Wr1w [4 * 8 * 2560];
__device__ __align__(16) half g_Wr2w [16 * 8 * 2560];

// ---------------- helpers ----------------------------------------------------
__device__ __forceinline__ float sp_beta(float x, float beta, float invb) {
    float t = beta * x;
    if (t > 20.f) return x;
    return log1pf(expf(t)) * invb;
}

__device__ __forceinline__ uint32_t smem_u32(const void* p) {
    uint32_t a;
    asm("{ .reg .u64 t; cvta.to.shared.u64 t, %1; cvt.u32.u64 %0, t; }" : "=r"(a) : "l"(p));
    return a;
}

__device__ __forceinline__ size_t act_idx(int brow, int col, int K) {
    return ((size_t)((brow >> 7) * (K >> 5) + (col >> 5))) * 5120
         + (size_t)((brow & 127) * 40 + (col & 31));
}
__device__ __forceinline__ size_t w_idx(int wrow, int col, int K) {
    return ((size_t)((wrow >> 6) * (K >> 5) + (col >> 5))) * 2560
         + (size_t)((wrow & 63) * 40 + (col & 31));
}

__device__ __forceinline__ void mbar_init(uint32_t m, uint32_t cnt) {
    asm volatile("mbarrier.init.shared.b64 [%0], %1;" :: "r"(m), "r"(cnt) : "memory");
}
__device__ __forceinline__ void mbar_expect(uint32_t m, uint32_t tx) {
    asm volatile("mbarrier.arrive.expect_tx.shared.b64 _, [%0], %1;" :: "r"(m), "r"(tx) : "memory");
}
__device__ __forceinline__ void mbar_wait(uint32_t m, uint32_t ph) {
    asm volatile(
        "{\n\t.reg .pred P;\n\t"
        "W%=:\n\t"
        "mbarrier.try_wait.parity.acquire.cta.shared::cta.b64 P, [%0], %1, 0x989680;\n\t"
        "@!P bra W%=;\n\t}"
        :: "r"(m), "r"(ph) : "memory");
}
__device__ __forceinline__ void bulk_g2s(uint32_t dst, const void* src,
                                         uint32_t bytes, uint32_t m) {
    asm volatile(
        "cp.async.bulk.shared::cta.global.mbarrier::complete_tx::bytes [%0], [%1], %2, [%3];"
        :: "r"(dst), "l"(src), "r"(bytes), "r"(m) : "memory");
}

__device__ __forceinline__ void cvt4(float4 v, half* dst, size_t off) {
    half2 h0 = __floats2half2_rn(v.x, v.y);
    half2 h1 = __floats2half2_rn(v.z, v.w);
    uint2 u;
    u.x = *(uint32_t*)&h0; u.y = *(uint32_t*)&h1;
    *(uint2*)(dst + off) = u;
}

// ---------------- batched fp32 -> fp16 tiled conversion ----------------------
#define S_IT    2097152
#define S_H     524288
#define S_ZM    524288
#define S_W1024 65536
#define S_W256  16384
#define S_WI2T  4096
#define S_WR2   65536
#define S_WV    1024
#define CVT_TOTAL (S_IT + S_H + S_ZM + 2*S_W1024 + 4*S_W256 + S_WI2T + S_W256 + S_WR2 + S_WV)

__device__ __forceinline__ void cvt_one(long o,
    const float4* It, const float4* h, const float4* zm,
    const float4* Wpmu, const float4* Wplv, const float4* Wz2h, const float4* Wh2h,
    const float4* Wprmu, const float4* Wprlv, const float4* Wi2t,
    const float4* Wr1, const float4* Wr2, const float4* Wv)
{
    long e;
    if (o < S_IT)   { e = o*4; cvt4(It[o],   g_It,  act_idx((int)(e>>10), (int)(e&1023), DIN)); return; } o -= S_IT;
    if (o < S_H)    { e = o*4; cvt4(h[o],    g_h,   act_idx((int)(e>>8),  (int)(e&255),  DH));  return; } o -= S_H;
    if (o < S_ZM)   { e = o*4; cvt4(zm[o],   g_zm,  act_idx((int)(e>>8),  (int)(e&255),  DZ));  return; } o -= S_ZM;
    if (o < S_W1024){ e = o*4; cvt4(Wpmu[o], g_Wpmu, w_idx((int)(e>>10), (int)(e&1023), DIN)); return; } o -= S_W1024;
    if (o < S_W1024){ e = o*4; cvt4(Wplv[o], g_Wplv, w_idx((int)(e>>10), (int)(e&1023), DIN)); return; } o -= S_W1024;
    if (o < S_W256) { e = o*4; cvt4(Wz2h[o], g_Wz2h, w_idx((int)(e>>8),  (int)(e&255),  DZ));  return; } o -= S_W256;
    if (o < S_W256) { e = o*4; cvt4(Wh2h[o], g_Wh2h, w_idx((int)(e>>8),  (int)(e&255),  DH));  return; } o -= S_W256;
    if (o < S_W256) { e = o*4; cvt4(Wprmu[o], g_Wprmu, w_idx((int)(e>>8), (int)(e&255), DH));  return; } o -= S_W256;
    if (o < S_W256) { e = o*4; cvt4(Wprlv[o], g_Wprlv, w_idx((int)(e>>8), (int)(e&255), DH));  return; } o -= S_W256;
    if (o < S_WI2T) { e = o*4; cvt4(Wi2t[o], g_Wi2t, w_idx((int)(e>>10), (int)(e&1023), DIN)); return; } o -= S_WI2T;
    if (o < S_W256) { e = o*4; cvt4(Wr1[o],  g_Wr1w, w_idx((int)(e>>8),  (int)(e&255),  DZ));  return; } o -= S_W256;
    if (o < S_WR2)  { e = o*4; cvt4(Wr2[o],  g_Wr2w, w_idx((int)(e>>8),  (int)(e&255),  DREC)); return; } o -= S_WR2;
    if (o < S_WV)   {
        e = o*4;
        float4 v = Wv[o];
        v.x = fmaxf(v.x, 0.f); v.y = fmaxf(v.y, 0.f);
        v.z = fmaxf(v.z, 0.f); v.w = fmaxf(v.w, 0.f);
        cvt4(v, g_Wv, w_idx((int)(e>>8), (int)(e&255), DZ));
    }
}

__global__ __launch_bounds__(256)
void cvt_all(const float4* __restrict__ It, const float4* __restrict__ h,
             const float4* __restrict__ zm,
             const float4* __restrict__ Wpmu, const float4* __restrict__ Wplv,
             const float4* __restrict__ Wz2h, const float4* __restrict__ Wh2h,
             const float4* __restrict__ Wprmu, const float4* __restrict__ Wprlv,
             const float4* __restrict__ Wi2t, const float4* __restrict__ Wr1,
             const float4* __restrict__ Wr2, const float4* __restrict__ Wv)
{
    if (blockIdx.x == 0 && threadIdx.x < 3)   // folded zero_acc
        g_acc[threadIdx.x] = 0.0;
    const long stride = (long)gridDim.x * 256;
    long i = (long)blockIdx.x * 256 + threadIdx.x;
#pragma unroll
    for (int u = 0; u < 4; ++u, i += stride)
        if (i < CVT_TOTAL)
            cvt_one(i, It, h, zm, Wpmu, Wplv, Wz2h, Wh2h, Wprmu, Wprlv, Wi2t, Wr1, Wr2, Wv);
}

// ============================================================================
// GEMM: fp16 single-term, bulk-copy staged. BMT x 64, BK=32, 2*BMT threads.
// Warp tiles 32x32. 3-stage mbarrier pipeline.
// ============================================================================
#define P_PITCH 40
#define OFF_B(BMT) ((BMT) * 80)
#define STAGEB(BMT) ((BMT) * 80 + 5120)

#define GEMM_COMPUTE_CHUNK(sAh_, sBh_)                                                    \
    _Pragma("unroll")                                                                      \
    for (int ks = 0; ks < 2; ++ks) {                                                       \
        wmma::fragment<wmma::matrix_a, 16, 16, 16, half, wmma::row_major> fa[2];           \
        wmma::fragment<wmma::matrix_b, 16, 16, 16, half, wmma::col_major> fb[2];           \
        _Pragma("unroll")                                                                  \
        for (int tm = 0; tm < 2; ++tm)                                                     \
            wmma::load_matrix_sync(fa[tm], sAh_ + (wm * 32 + tm * 16) * P_PITCH + ks * 16, P_PITCH); \
        _Pragma("unroll")                                                                  \
        for (int tn = 0; tn < 2; ++tn)                                                     \
            wmma::load_matrix_sync(fb[tn], sBh_ + (wn * 32 + tn * 16) * P_PITCH + ks * 16, P_PITCH); \
        _Pragma("unroll")                                                                  \
        for (int tm = 0; tm < 2; ++tm)                                                     \
            _Pragma("unroll")                                                              \
            for (int tn = 0; tn < 2; ++tn)                                                 \
                wmma::mma_sync(acc[tm][tn], fa[tm], fb[tn], acc[tm][tn]);                  \
    }

// ---------------- front mega-GEMM (BM=128, 256 thr, 4 CTA/SM) ----------------
// bx 0-3 mu_q | 4-7 sigma_q | 8 ti | 9-12 mu_p | 13-16 sigma_p | 17-20 h(dual)
__global__ __launch_bounds__(256, 4)
void gemm_front(float* __restrict__ C_muq, float* __restrict__ C_sigq,
                float* __restrict__ C_ti,  float* __restrict__ C_mup,
                float* __restrict__ C_sigp, float* __restrict__ C_h)
{
    extern __shared__ __align__(16) char smem[];
    __shared__ __align__(8) uint64_t mbars[3];

    const int tid = threadIdx.x;
    const int wid = tid >> 5;
    const int bx = blockIdx.x, by = blockIdx.y;
    const int wm = wid >> 1, wn = wid & 1;

    int route;
    if (bx < 4) route = 0; else if (bx < 8) route = 1; else if (bx == 8) route = 2;
    else if (bx < 13) route = 3; else if (bx < 17) route = 4; else route = 5;

    const half *Ah, *Bh;
    int K, nt;
    switch (route) {
        case 0: Ah = g_It; Bh = g_Wpmu; K = DIN; nt = bx & 3; break;
        case 1: Ah = g_It; Bh = g_Wplv; K = DIN; nt = bx & 3; break;
        case 2: Ah = g_It; Bh = g_Wi2t; K = DIN; nt = 0; break;
        case 3: Ah = g_h;  Bh = g_Wprmu; K = DH; nt = bx - 9; break;
        case 4: Ah = g_h;  Bh = g_Wprlv; K = DH; nt = bx - 13; break;
        default: Ah = g_zm; Bh = g_Wz2h; K = DZ; nt = bx - 17; break;
    }
    const int nc0 = K / 32;
    const int nc = (route == 5) ? nc0 + DH / 32 : nc0;

    const uint32_t smb = smem_u32(smem);
    const uint32_t mbb = smem_u32(mbars);

    if (tid == 0)
        for (int s = 0; s < 3; ++s) mbar_init(mbb + s * 8, 1);
    __syncthreads();

    auto issue = [&](int c) {
        if (tid != 0) return;
        const half *Asrc, *Bsrc;
        int Kc, kci;
        if (route == 5 && c >= nc0) {
            Asrc = g_h; Bsrc = g_Wh2h; Kc = DH; kci = c - nc0;
        } else {
            Asrc = Ah; Bsrc = Bh; Kc = K; kci = c;
        }
        int s = c % 3;
        uint32_t mb = mbb + s * 8;
        uint32_t dst = smb + s * 15360;
        mbar_expect(mb, 15360);
        bulk_g2s(dst, Asrc + ((size_t)(by * (Kc >> 5) + kci)) * 5120, 10240, mb);
        bulk_g2s(dst + 10240, Bsrc + ((size_t)(nt * (Kc >> 5) + kci)) * 2560, 5120, mb);
    };

    wmma::fragment<wmma::accumulator, 16, 16, 16, float> acc[2][2];
#pragma unroll
    for (int tm = 0; tm < 2; ++tm)
#pragma unroll
        for (int tn = 0; tn < 2; ++tn)
            wmma::fill_fragment(acc[tm][tn], 0.f);

    issue(0);
    if (nc > 1) issue(1);
    for (int c = 0; c < nc; ++c) {
        mbar_wait(mbb + (c % 3) * 8, (uint32_t)((c / 3) & 1));
        __syncthreads();
        if (c + 2 < nc) issue(c + 2);
        const half* sAh = (const half*)(smem + (c % 3) * 15360);
        const half* sBh = (const half*)(smem + (c % 3) * 15360 + 10240);
        GEMM_COMPUTE_CHUNK(sAh, sBh)
    }

    __syncthreads();
    float* sC = (float*)smem;
#pragma unroll
    for (int tm = 0; tm < 2; ++tm)
#pragma unroll
        for (int tn = 0; tn < 2; ++tn)
            wmma::store_matrix_sync(sC + (wm * 32 + tm * 16) * 64 + wn * 32 + tn * 16,
                                    acc[tm][tn], 64, wmma::mem_row_major);
    __syncthreads();

    if (route == 2) {   // ti
        int row = tid >> 1, c0 = (tid & 1) * 8;
        size_t gb = (size_t)(by * 128 + row) * DT + c0;
        *(float4*)(C_ti + gb)     = *(const float4*)(sC + row * 64 + c0);
        *(float4*)(C_ti + gb + 4) = *(const float4*)(sC + row * 64 + c0 + 4);
        return;
    }

    float* Cd;
    int col0;
    switch (route) {
        case 0: Cd = C_muq;  col0 = (bx & 3) * 64; break;
        case 1: Cd = C_sigq; col0 = (bx & 3) * 64; break;
        case 3: Cd = C_mup;  col0 = (bx - 9) * 64; break;
        case 4: Cd = C_sigp; col0 = (bx - 13) * 64; break;
        default: Cd = C_h;   col0 = (bx - 17) * 64; break;
    }
    const bool do_sp = (route == 4);
    const int tx = tid & 15, ty = tid >> 4;
#pragma unroll
    for (int i = 0; i < 8; ++i) {
        int row = ty * 8 + i;
        int col = col0 + tx * 4;
        size_t gbase = (size_t)(by * 128 + row) * DZ + col;
        float4 v = *(const float4*)(sC + row * 64 + tx * 4);
        float4 o;
        o.x = do_sp ? sp_beta(v.x, 1.2f, 1.f/1.2f) : fmaxf(v.x, 0.f);
        o.y = do_sp ? sp_beta(v.y, 1.2f, 1.f/1.2f) : fmaxf(v.y, 0.f);
        o.z = do_sp ? sp_beta(v.z, 1.2f, 1.f/1.2f) : fmaxf(v.z, 0.f);
        o.w = do_sp ? sp_beta(v.w, 1.2f, 1.f/1.2f) : fmaxf(v.w, 0.f);
        *(float4*)(Cd + gbase) = o;
        if (do_sp)   // fp16 sigma_p, tiled, for theta GEMM
            cvt4(o, g_sp, act_idx(by * 128 + row, col, DZ));
    }
}

// ---------------- back GEMMs: MODE 3 = r1 emit, 4 = rec2, 5 = theta ----------
template<int MODE, int BMT>
__global__ __launch_bounds__(BMT * 2, (BMT == 128) ? 4 : 6)
void tc_gemm(const half* __restrict__ A0h, int K0,
             const half* __restrict__ B0h,
             float* __restrict__ C0, const float* __restrict__ aux0,
             const float* __restrict__ aux1, half* __restrict__ Chi)
{
    extern __shared__ __align__(16) char smem[];
    __shared__ __align__(8) uint64_t mbars[3];
    __shared__ float red[256];

    const int tid = threadIdx.x;
    const int wid = tid >> 5;
    const int bx = blockIdx.x, by = blockIdx.y;
    const int wm = wid >> 1, wn = wid & 1;
    const int nc = K0 / 32;
    const uint32_t smb = smem_u32(smem);
    const uint32_t mbb = smem_u32(mbars);
    const int rowbase = by * BMT;

    if (tid == 0)
        for (int s = 0; s < 3; ++s) mbar_init(mbb + s * 8, 1);
    __syncthreads();

    auto issue = [&](int c) {
        if (tid != 0) return;
        int s = c % 3;
        uint32_t mb = mbb + s * 8;
        uint32_t dst = smb + s * STAGEB(BMT);
        mbar_expect(mb, STAGEB(BMT));
        const half* asrc = A0h + ((size_t)((rowbase >> 7) * (K0 >> 5) + c)) * 5120
                                + (size_t)(rowbase & 127) * 40;
        bulk_g2s(dst, asrc, BMT * 80, mb);
        bulk_g2s(dst + OFF_B(BMT), B0h + ((size_t)(bx * (K0 >> 5) + c)) * 2560, 5120, mb);
    };

    wmma::fragment<wmma::accumulator, 16, 16, 16, float> acc[2][2];
#pragma unroll
    for (int tm = 0; tm < 2; ++tm)
#pragma unroll
        for (int tn = 0; tn < 2; ++tn)
            wmma::fill_fragment(acc[tm][tn], 0.f);

    issue(0);
    if (nc > 1) issue(1);
    for (int c = 0; c < nc; ++c) {
        mbar_wait(mbb + (c % 3) * 8, (uint32_t)((c / 3) & 1));
        __syncthreads();
        if (c + 2 < nc) issue(c + 2);
        const half* sAh = (const half*)(smem + (c % 3) * STAGEB(BMT));
        const half* sBh = (const half*)(smem + (c % 3) * STAGEB(BMT) + OFF_B(BMT));
        GEMM_COMPUTE_CHUNK(sAh, sBh)
    }

    __syncthreads();
    float* sC = (float*)smem;
#pragma unroll
    for (int tm = 0; tm < 2; ++tm)
#pragma unroll
        for (int tn = 0; tn < 2; ++tn)
            wmma::store_matrix_sync(sC + (wm * 32 + tm * 16) * 64 + wn * 32 + tn * 16,
                                    acc[tm][tn], 64, wmma::mem_row_major);
    __syncthreads();

    if (MODE == 5) {   // theta finalize (cols 0..15 only)
        int row = tid >> 1, c0 = (tid & 1) * 8;
        size_t gb = (size_t)(rowbase + row) * DT + c0;
#pragma unroll
        for (int j = 0; j < 8; ++j) {
            float dot = sC[row * 64 + c0 + j];
            float th_h = 0.5f * aux0[gb + j] + 0.1f * aux1[gb + j] - dot;
            float u = 0.5f * th_h;
            C0[gb + j] = 0.001f * ((u > 20.f) ? th_h : 2.0f * log1pf(expf(u)));
        }
        return;
    }

    float lsum = 0.f;
    const int tx = tid & 15, ty = tid >> 4;
    const int N = (MODE == 4) ? 1024 : 256;
    const int col0 = bx * 64;
#pragma unroll
    for (int i = 0; i < 8; ++i) {
        int row = ty * 8 + i;
        int col = col0 + tx * 4;
        size_t gbase = (size_t)(rowbase + row) * N + col;
        float4 v = *(const float4*)(sC + row * 64 + tx * 4);
        if (MODE == 3) {
            cvt4(v, Chi, act_idx(rowbase + row, col, DREC));   // r1 fp16 tiled
        } else {
            float4 a0 = *(const float4*)(aux0 + gbase);
            float4 o;
            o.x = 1.f / (1.f + expf(-v.x)); { float d = a0.x - o.x; lsum += d * d; }
            o.y = 1.f / (1.f + expf(-v.y)); { float d = a0.y - o.y; lsum += d * d; }
            o.z = 1.f / (1.f + expf(-v.z)); { float d = a0.z - o.z; lsum += d * d; }
            o.w = 1.f / (1.f + expf(-v.w)); { float d = a0.w - o.w; lsum += d * d; }
            *(float4*)(C0 + gbase) = o;
        }
    }

    if (MODE == 4) {
        red[tid] = lsum;
        __syncthreads();
#pragma unroll
        for (int s = BMT; s > 0; s >>= 1) {
            if (tid < s) red[tid] += red[tid + s];
            __syncthreads();
        }
        if (tid == 0) atomicAdd(&g_acc[0], (double)red[0]);
    }
}

// ---------------- z elementwise: 16 rows/block, serial row loop --------------
__global__ __launch_bounds__(256)
void z_elem(const float* __restrict__ W_t2z,
            const float* __restrict__ eps_z,
            const float* __restrict__ eps_zhat,
            float* __restrict__ z_out,
            float* __restrict__ zhat_out)
{
    __shared__ float sWt[DT][DZ + 4];
    __shared__ float sTh[16][DT];
    __shared__ float red[256];

    const int tid = threadIdx.x;
    const int row0 = blockIdx.x * 16;

    for (int idx = tid; idx < DZ * DT; idx += 256) {
        int n = idx >> 4, t = idx & 15;
        sWt[t][n] = fmaxf(W_t2z[idx], 0.f);
    }
    if (tid < 256)
        sTh[tid >> 4][tid & 15] = g_theta[(size_t)row0 * DT + tid];
    __syncthreads();

    const int rb = tid >> 6;       // base row within group of 4
    const int q = tid & 63;        // column quad
    float e_sum = 0.f, t_sum = 0.f;

#pragma unroll 1
    for (int p = 0; p < 4; ++p) {
        const int r = rb + p * 4;
        const int row = row0 + r;
        const size_t idx = (size_t)row * DZ + q * 4;

        float4 muq = *(const float4*)(g_mu_q + idx);
        float4 sgq = *(const float4*)(g_sigma_q + idx);
        float4 epz = *(const float4*)(eps_z + idx);
        float4 eph = *(const float4*)(eps_zhat + idx);
        float4 mup = *(const float4*)(g_mu_p + idx);
        float4 sp4 = *(const float4*)(g_sigma_p + idx);

        float4 thr = make_float4(0.f, 0.f, 0.f, 0.f);
#pragma unroll
        for (int t = 0; t < DT; ++t) {
            float th = sTh[r][t];
            float4 w = *(const float4*)(&sWt[t][q * 4]);
            thr.x = fmaf(th, w.x, thr.x);
            thr.y = fmaf(th, w.y, thr.y);
            thr.z = fmaf(th, w.z, thr.z);
            thr.w = fmaf(th, w.w, thr.w);
        }

        float4 zv, zh;
        float raw;
        raw = fminf(fmaxf(fmaf(epz.x, sgq.x, muq.x), 0.f), 1.f);
        zv.x = fmaxf(raw - 10.f * thr.x, 0.f);  zh.x = fmaf(eph.x, sp4.x, mup.x);
        raw = fminf(fmaxf(fmaf(epz.y, sgq.y, muq.y), 0.f), 1.f);
        zv.y = fmaxf(raw - 10.f * thr.y, 0.f);  zh.y = fmaf(eph.y, sp4.y, mup.y);
        raw = fminf(fmaxf(fmaf(epz.z, sgq.z, muq.z), 0.f), 1.f);
        zv.z = fmaxf(raw - 10.f * thr.z, 0.f);  zh.z = fmaf(eph.z, sp4.z, mup.z);
        raw = fminf(fmaxf(fmaf(epz.w, sgq.w, muq.w), 0.f), 1.f);
        zv.w = fmaxf(raw - 10.f * thr.w, 0.f);  zh.w = fmaf(eph.w, sp4.w, mup.w);

        *(float4*)(z_out + idx) = zv;
        *(float4*)(zhat_out + idx) = zh;
        cvt4(zv, g_z, act_idx(row, q * 4, DZ));

        e_sum += zv.x + zv.y + zv.z + zv.w;
        float d;
        d = zv.x - zh.x; t_sum = fmaf(d, d, t_sum);
        d = zv.y - zh.y; t_sum = fmaf(d, d, t_sum);
        d = zv.z - zh.z; t_sum = fmaf(d, d, t_sum);
        d = zv.w - zh.w; t_sum = fmaf(d, d, t_sum);
    }

    red[tid] = e_sum; __syncthreads();
#pragma unroll
    for (int s = 128; s > 0; s >>= 1) { if (tid < s) red[tid] += red[tid + s]; __syncthreads(); }
    if (tid == 0) atomicAdd(&g_acc[2], (double)red[0]);
    __syncthreads();
    red[tid] = t_sum; __syncthreads();
#pragma unroll
    for (int s = 128; s > 0; s >>= 1) { if (tid < s) red[tid] += red[tid + s]; __syncthreads(); }
    if (tid == 0) atomicAdd(&g_acc[1], (double)red[0]);
}

// ---------------- finalize ----------------------------------------------------
__global__ void finalize_kernel(float* __restrict__ out_scalars) {
    if (threadIdx.x == 0) {
        out_scalars[0] = (float)(g_acc[0] / (double)((size_t)BATCH * DIN));
        out_scalars[1] = (float)(g_acc[1] / (double)((size_t)BATCH * DZ));
        out_scalars[2] = (float)(g_acc[2] / (double)((size_t)BATCH * DZ));
    }
}

// ---------------- launch -----------------------------------------------------
extern "C" void kernel_launch(void* const* d_in, const int* in_sizes, int n_in,
                              void* d_out, int out_size)
{
    const float* I_t        = (const float*)d_in[0];
    const float* h_m_1      = (const float*)d_in[1];
    const float* z_m_1      = (const float*)d_in[2];
    const float* theta_m_1  = (const float*)d_in[3];
    const float* eps_z      = (const float*)d_in[4];
    const float* eps_zhat   = (const float*)d_in[5];
    const float* W_post_mu  = (const float*)d_in[6];
    const float* W_post_lv  = (const float*)d_in[7];
    const float* W_z2h      = (const float*)d_in[8];
    const float* W_h2h      = (const float*)d_in[9];
    const float* W_prior_mu = (const float*)d_in[10];
    const float* W_prior_lv = (const float*)d_in[11];
    const float* W_i2t      = (const float*)d_in[12];
    const float* W_vip2t    = (const float*)d_in[13];
    const float* W_t2z      = (const float*)d_in[14];
    const float* W_rec1     = (const float*)d_in[15];
    const float* W_rec2     = (const float*)d_in[16];

    float* out       = (float*)d_out;
    float* out_ihat  = out;
    float* out_z     = out + (size_t)BATCH * DIN;
    float* out_h     = out_z + (size_t)BATCH * DZ;
    float* out_zhat  = out_h + (size_t)BATCH * DH;
    float* out_scal  = out_zhat + (size_t)BATCH * DZ;

    float *mu_q, *sigma_q, *sigma_p, *mu_p, *ti, *theta;
    cudaGetSymbolAddress((void**)&mu_q,    g_mu_q);
    cudaGetSymbolAddress((void**)&sigma_q, g_sigma_q);
    cudaGetSymbolAddress((void**)&sigma_p, g_sigma_p);
    cudaGetSymbolAddress((void**)&mu_p,    g_mu_p);
    cudaGetSymbolAddress((void**)&ti,      g_ti);
    cudaGetSymbolAddress((void**)&theta,   g_theta);
    half *z_t, *sp_t, *r1_t, *Wv_t, *Wr1_t, *Wr2_t;
    cudaGetSymbolAddress((void**)&z_t,  g_z);
    cudaGetSymbolAddress((void**)&sp_t, g_sp);
    cudaGetSymbolAddress((void**)&r1_t, g_r1);
    cudaGetSymbolAddress((void**)&Wv_t, g_Wv);
    cudaGetSymbolAddress((void**)&Wr1_t, g_Wr1w);
    cudaGetSymbolAddress((void**)&Wr2_t, g_Wr2w);

    const int SM128 = 3 * STAGEB(128);   // 46080
    const int SM64  = 3 * STAGEB(64);    // 30720
    cudaFuncSetAttribute(gemm_front, cudaFuncAttributeMaxDynamicSharedMemorySize, SM128);
    cudaFuncSetAttribute(tc_gemm<3, 64>,  cudaFuncAttributeMaxDynamicSharedMemorySize, SM64);
    cudaFuncSetAttribute(tc_gemm<4, 128>, cudaFuncAttributeMaxDynamicSharedMemorySize, SM128);
    cudaFuncSetAttribute(tc_gemm<5, 64>,  cudaFuncAttributeMaxDynamicSharedMemorySize, SM64);

    const dim3 blk(256);
    const dim3 blk64(128);

    cvt_all<<<(CVT_TOTAL + 1023) / 1024, blk>>>(
        (const float4*)I_t, (const float4*)h_m_1, (const float4*)z_m_1,
        (const float4*)W_post_mu, (const float4*)W_post_lv,
        (const float4*)W_z2h, (const float4*)W_h2h,
        (const float4*)W_prior_mu, (const float4*)W_prior_lv,
        (const float4*)W_i2t, (const float4*)W_rec1, (const float4*)W_rec2,
        (const float4*)W_vip2t);

    gemm_front<<<dim3(21, BATCH / 128), blk, SM128>>>(
        mu_q, sigma_q, ti, mu_p, sigma_p, out_h);

    // theta = 0.001*softplus_0.5(0.5*theta_m_1 + 0.1*ti - sigma_p @ relu(Wv)^T)
    tc_gemm<5, 64><<<dim3(1, BATCH / 64), blk64, SM64>>>(
        sp_t, DZ, Wv_t, theta, theta_m_1, ti, nullptr);

    z_elem<<<BATCH / 16, blk>>>(W_t2z, eps_z, eps_zhat, out_z, out_zhat);

    tc_gemm<3, 64><<<dim3(4, BATCH / 64), blk64, SM64>>>(
        z_t, DZ, Wr1_t, nullptr, nullptr, nullptr, r1_t);

    tc_gemm<4, 128><<<dim3(16, BATCH / 128), blk, SM128>>>(
        r1_t, DREC, Wr2_t, out_ihat, I_t, nullptr, nullptr);

    finalize_kernel<<<1, 32>>>(out_scal);
    (void)in_sizes; (void)n_in; (void)out_size;
}

// round 17
// speedup vs baseline: 1.4088x; 1.4088x over previous
#include <cuda_runtime.h>
#include <cuda_fp16.h>
#include <mma.h>
#include <math.h>
#include <stdint.h>

using namespace nvcuda;

#define BATCH 8192
#define DIN   1024
#define DZ    256
#define DH    256
#define DT    16
#define DREC  256

// tiled fp16 layout:
//   activation tile: 128 rows x 40-half pitch (cols 0..31 valid) = 5120 halves
//   weight tile:      64 rows x 40-half pitch                    = 2560 halves

// ---------------- scratch (device globals) ----------------------------------
__device__ float g_mu_q   [BATCH * DZ];
__device__ float g_sigma_q[BATCH * DZ];
__device__ float g_sigma_p[BATCH * DZ];
__device__ float g_mu_p   [BATCH * DZ];
__device__ float g_ti     [BATCH * DT];
__device__ float g_theta  [BATCH * DT];
__device__ double g_acc[3];

__device__ __align__(16) half g_It [64 * 32 * 5120];
__device__ __align__(16) half g_h  [64 * 8 * 5120];
__device__ __align__(16) half g_zm [64 * 8 * 5120];
__device__ __align__(16) half g_z  [64 * 8 * 5120];
__device__ __align__(16) half g_sp [64 * 8 * 5120];
__device__ __align__(16) half g_r1 [64 * 8 * 5120];
__device__ __align__(16) half g_Wpmu [4 * 32 * 2560];
__device__ __align__(16) half g_Wplv [4 * 32 * 2560];
__device__ __align__(16) half g_Wz2h [4 * 8 * 2560];
__device__ __align__(16) half g_Wh2h [4 * 8 * 2560];
__device__ __align__(16) half g_Wprmu[4 * 8 * 2560];
__device__ __align__(16) half g_Wprlv[4 * 8 * 2560];
__device__ __align__(16) half g_Wi2t [1 * 32 * 2560];   // rows 16..63 garbage (cols discarded)
__device__ __align__(16) half g_Wv   [1 * 8 * 2560];    // relu applied; rows 16..63 garbage
__device__ __align__(16) half g_Wr1w [4 * 8 * 2560];
__device__ __align__(16) half g_Wr2w [16 * 8 * 2560];

// ---------------- helpers ----------------------------------------------------
__device__ __forceinline__ float sp_beta(float x, float beta, float invb) {
    float t = beta * x;
    if (t > 20.f) return x;
    return log1pf(expf(t)) * invb;
}

__device__ __forceinline__ uint32_t smem_u32(const void* p) {
    uint32_t a;
    asm("{ .reg .u64 t; cvta.to.shared.u64 t, %1; cvt.u32.u64 %0, t; }" : "=r"(a) : "l"(p));
    return a;
}

__device__ __forceinline__ size_t act_idx(int brow, int col, int K) {
    return ((size_t)((brow >> 7) * (K >> 5) + (col >> 5))) * 5120
         + (size_t)((brow & 127) * 40 + (col & 31));
}
__device__ __forceinline__ size_t w_idx(int wrow, int col, int K) {
    return ((size_t)((wrow >> 6) * (K >> 5) + (col >> 5))) * 2560
         + (size_t)((wrow & 63) * 40 + (col & 31));
}

__device__ __forceinline__ void mbar_init(uint32_t m, uint32_t cnt) {
    asm volatile("mbarrier.init.shared.b64 [%0], %1;" :: "r"(m), "r"(cnt) : "memory");
}
__device__ __forceinline__ void mbar_expect(uint32_t m, uint32_t tx) {
    asm volatile("mbarrier.arrive.expect_tx.shared.b64 _, [%0], %1;" :: "r"(m), "r"(tx) : "memory");
}
__device__ __forceinline__ void mbar_wait(uint32_t m, uint32_t ph) {
    asm volatile(
        "{\n\t.reg .pred P;\n\t"
        "W%=:\n\t"
        "mbarrier.try_wait.parity.acquire.cta.shared::cta.b64 P, [%0], %1, 0x989680;\n\t"
        "@!P bra W%=;\n\t}"
        :: "r"(m), "r"(ph) : "memory");
}
__device__ __forceinline__ void bulk_g2s(uint32_t dst, const void* src,
                                         uint32_t bytes, uint32_t m) {
    asm volatile(
        "cp.async.bulk.shared::cta.global.mbarrier::complete_tx::bytes [%0], [%1], %2, [%3];"
        :: "r"(dst), "l"(src), "r"(bytes), "r"(m) : "memory");
}

__device__ __forceinline__ void cvt4(float4 v, half* dst, size_t off) {
    half2 h0 = __floats2half2_rn(v.x, v.y);
    half2 h1 = __floats2half2_rn(v.z, v.w);
    uint2 u;
    u.x = *(uint32_t*)&h0; u.y = *(uint32_t*)&h1;
    *(uint2*)(dst + off) = u;
}

// ---------------- batched fp32 -> fp16 tiled conversion ----------------------
#define S_IT    2097152
#define S_H     524288
#define S_ZM    524288
#define S_W1024 65536
#define S_W256  16384
#define S_WI2T  4096
#define S_WR2   65536
#define S_WV    1024
#define CVT_TOTAL (S_IT + S_H + S_ZM + 2*S_W1024 + 4*S_W256 + S_WI2T + S_W256 + S_WR2 + S_WV)

__device__ __forceinline__ void cvt_one(long o,
    const float4* It, const float4* h, const float4* zm,
    const float4* Wpmu, const float4* Wplv, const float4* Wz2h, const float4* Wh2h,
    const float4* Wprmu, const float4* Wprlv, const float4* Wi2t,
    const float4* Wr1, const float4* Wr2, const float4* Wv)
{
    long e;
    if (o < S_IT)   { e = o*4; cvt4(It[o],   g_It,  act_idx((int)(e>>10), (int)(e&1023), DIN)); return; } o -= S_IT;
    if (o < S_H)    { e = o*4; cvt4(h[o],    g_h,   act_idx((int)(e>>8),  (int)(e&255),  DH));  return; } o -= S_H;
    if (o < S_ZM)   { e = o*4; cvt4(zm[o],   g_zm,  act_idx((int)(e>>8),  (int)(e&255),  DZ));  return; } o -= S_ZM;
    if (o < S_W1024){ e = o*4; cvt4(Wpmu[o], g_Wpmu, w_idx((int)(e>>10), (int)(e&1023), DIN)); return; } o -= S_W1024;
    if (o < S_W1024){ e = o*4; cvt4(Wplv[o], g_Wplv, w_idx((int)(e>>10), (int)(e&1023), DIN)); return; } o -= S_W1024;
    if (o < S_W256) { e = o*4; cvt4(Wz2h[o], g_Wz2h, w_idx((int)(e>>8),  (int)(e&255),  DZ));  return; } o -= S_W256;
    if (o < S_W256) { e = o*4; cvt4(Wh2h[o], g_Wh2h, w_idx((int)(e>>8),  (int)(e&255),  DH));  return; } o -= S_W256;
    if (o < S_W256) { e = o*4; cvt4(Wprmu[o], g_Wprmu, w_idx((int)(e>>8), (int)(e&255), DH));  return; } o -= S_W256;
    if (o < S_W256) { e = o*4; cvt4(Wprlv[o], g_Wprlv, w_idx((int)(e>>8), (int)(e&255), DH));  return; } o -= S_W256;
    if (o < S_WI2T) { e = o*4; cvt4(Wi2t[o], g_Wi2t, w_idx((int)(e>>10), (int)(e&1023), DIN)); return; } o -= S_WI2T;
    if (o < S_W256) { e = o*4; cvt4(Wr1[o],  g_Wr1w, w_idx((int)(e>>8),  (int)(e&255),  DZ));  return; } o -= S_W256;
    if (o < S_WR2)  { e = o*4; cvt4(Wr2[o],  g_Wr2w, w_idx((int)(e>>8),  (int)(e&255),  DREC)); return; } o -= S_WR2;
    if (o < S_WV)   {
        e = o*4;
        float4 v = Wv[o];
        v.x = fmaxf(v.x, 0.f); v.y = fmaxf(v.y, 0.f);
        v.z = fmaxf(v.z, 0.f); v.w = fmaxf(v.w, 0.f);
        cvt4(v, g_Wv, w_idx((int)(e>>8), (int)(e&255), DZ));
    }
}

__global__ __launch_bounds__(256)
void cvt_all(const float4* __restrict__ It, const float4* __restrict__ h,
             const float4* __restrict__ zm,
             const float4* __restrict__ Wpmu, const float4* __restrict__ Wplv,
             const float4* __restrict__ Wz2h, const float4* __restrict__ Wh2h,
             const float4* __restrict__ Wprmu, const float4* __restrict__ Wprlv,
             const float4* __restrict__ Wi2t, const float4* __restrict__ Wr1,
             const float4* __restrict__ Wr2, const float4* __restrict__ Wv)
{
    if (blockIdx.x == 0 && threadIdx.x < 3)   // folded zero_acc
        g_acc[threadIdx.x] = 0.0;
    const long stride = (long)gridDim.x * 256;
    long i = (long)blockIdx.x * 256 + threadIdx.x;
#pragma unroll
    for (int u = 0; u < 4; ++u, i += stride)
        if (i < CVT_TOTAL)
            cvt_one(i, It, h, zm, Wpmu, Wplv, Wz2h, Wh2h, Wprmu, Wprlv, Wi2t, Wr1, Wr2, Wv);
}

// ============================================================================
// GEMM: fp16 single-term, bulk-copy staged. BMT x 64, BK=32, 2*BMT threads.
// Warp tiles 32x32. 3-stage mbarrier pipeline.
// ============================================================================
#define P_PITCH 40
#define OFF_B(BMT) ((BMT) * 80)
#define STAGEB(BMT) ((BMT) * 80 + 5120)

#define GEMM_COMPUTE_CHUNK(sAh_, sBh_)                                                    \
    _Pragma("unroll")                                                                      \
    for (int ks = 0; ks < 2; ++ks) {                                                       \
        wmma::fragment<wmma::matrix_a, 16, 16, 16, half, wmma::row_major> fa[2];           \
        wmma::fragment<wmma::matrix_b, 16, 16, 16, half, wmma::col_major> fb[2];           \
        _Pragma("unroll")                                                                  \
        for (int tm = 0; tm < 2; ++tm)                                                     \
            wmma::load_matrix_sync(fa[tm], sAh_ + (wm * 32 + tm * 16) * P_PITCH + ks * 16, P_PITCH); \
        _Pragma("unroll")                                                                  \
        for (int tn = 0; tn < 2; ++tn)                                                     \
            wmma::load_matrix_sync(fb[tn], sBh_ + (wn * 32 + tn * 16) * P_PITCH + ks * 16, P_PITCH); \
        _Pragma("unroll")                                                                  \
        for (int tm = 0; tm < 2; ++tm)                                                     \
            _Pragma("unroll")                                                              \
            for (int tn = 0; tn < 2; ++tn)                                                 \
                wmma::mma_sync(acc[tm][tn], fa[tm], fb[tn], acc[tm][tn]);                  \
    }

// ---------------- front mega-GEMM (BM=128, 256 thr, 4 CTA/SM) ----------------
// bx 0-3 mu_q | 4-7 sigma_q | 8 ti | 9-12 mu_p | 13-16 sigma_p | 17-20 h(dual)
__global__ __launch_bounds__(256, 4)
void gemm_front(float* __restrict__ C_muq, float* __restrict__ C_sigq,
                float* __restrict__ C_ti,  float* __restrict__ C_mup,
                float* __restrict__ C_sigp, float* __restrict__ C_h)
{
    extern __shared__ __align__(16) char smem[];
    __shared__ __align__(8) uint64_t mbars[3];

    const int tid = threadIdx.x;
    const int wid = tid >> 5;
    const int bx = blockIdx.x, by = blockIdx.y;
    const int wm = wid >> 1, wn = wid & 1;

    int route;
    if (bx < 4) route = 0; else if (bx < 8) route = 1; else if (bx == 8) route = 2;
    else if (bx < 13) route = 3; else if (bx < 17) route = 4; else route = 5;

    const half *Ah, *Bh;
    int K, nt;
    switch (route) {
        case 0: Ah = g_It; Bh = g_Wpmu; K = DIN; nt = bx & 3; break;
        case 1: Ah = g_It; Bh = g_Wplv; K = DIN; nt = bx & 3; break;
        case 2: Ah = g_It; Bh = g_Wi2t; K = DIN; nt = 0; break;
        case 3: Ah = g_h;  Bh = g_Wprmu; K = DH; nt = bx - 9; break;
        case 4: Ah = g_h;  Bh = g_Wprlv; K = DH; nt = bx - 13; break;
        default: Ah = g_zm; Bh = g_Wz2h; K = DZ; nt = bx - 17; break;
    }
    const int nc0 = K / 32;
    const int nc = (route == 5) ? nc0 + DH / 32 : nc0;

    const uint32_t smb = smem_u32(smem);
    const uint32_t mbb = smem_u32(mbars);

    if (tid == 0)
        for (int s = 0; s < 3; ++s) mbar_init(mbb + s * 8, 1);
    __syncthreads();

    auto issue = [&](int c) {
        if (tid != 0) return;
        const half *Asrc, *Bsrc;
        int Kc, kci;
        if (route == 5 && c >= nc0) {
            Asrc = g_h; Bsrc = g_Wh2h; Kc = DH; kci = c - nc0;
        } else {
            Asrc = Ah; Bsrc = Bh; Kc = K; kci = c;
        }
        int s = c % 3;
        uint32_t mb = mbb + s * 8;
        uint32_t dst = smb + s * 15360;
        mbar_expect(mb, 15360);
        bulk_g2s(dst, Asrc + ((size_t)(by * (Kc >> 5) + kci)) * 5120, 10240, mb);
        bulk_g2s(dst + 10240, Bsrc + ((size_t)(nt * (Kc >> 5) + kci)) * 2560, 5120, mb);
    };

    wmma::fragment<wmma::accumulator, 16, 16, 16, float> acc[2][2];
#pragma unroll
    for (int tm = 0; tm < 2; ++tm)
#pragma unroll
        for (int tn = 0; tn < 2; ++tn)
            wmma::fill_fragment(acc[tm][tn], 0.f);

    issue(0);
    if (nc > 1) issue(1);
    for (int c = 0; c < nc; ++c) {
        mbar_wait(mbb + (c % 3) * 8, (uint32_t)((c / 3) & 1));
        __syncthreads();
        if (c + 2 < nc) issue(c + 2);
        const half* sAh = (const half*)(smem + (c % 3) * 15360);
        const half* sBh = (const half*)(smem + (c % 3) * 15360 + 10240);
        GEMM_COMPUTE_CHUNK(sAh, sBh)
    }

    __syncthreads();
    float* sC = (float*)smem;
#pragma unroll
    for (int tm = 0; tm < 2; ++tm)
#pragma unroll
        for (int tn = 0; tn < 2; ++tn)
            wmma::store_matrix_sync(sC + (wm * 32 + tm * 16) * 64 + wn * 32 + tn * 16,
                                    acc[tm][tn], 64, wmma::mem_row_major);
    __syncthreads();

    if (route == 2) {   // ti
        int row = tid >> 1, c0 = (tid & 1) * 8;
        size_t gb = (size_t)(by * 128 + row) * DT + c0;
        *(float4*)(C_ti + gb)     = *(const float4*)(sC + row * 64 + c0);
        *(float4*)(C_ti + gb + 4) = *(const float4*)(sC + row * 64 + c0 + 4);
        return;
    }

    float* Cd;
    int col0;
    switch (route) {
        case 0: Cd = C_muq;  col0 = (bx & 3) * 64; break;
        case 1: Cd = C_sigq; col0 = (bx & 3) * 64; break;
        case 3: Cd = C_mup;  col0 = (bx - 9) * 64; break;
        case 4: Cd = C_sigp; col0 = (bx - 13) * 64; break;
        default: Cd = C_h;   col0 = (bx - 17) * 64; break;
    }
    const bool do_sp = (route == 4);
    const int tx = tid & 15, ty = tid >> 4;
#pragma unroll
    for (int i = 0; i < 8; ++i) {
        int row = ty * 8 + i;
        int col = col0 + tx * 4;
        size_t gbase = (size_t)(by * 128 + row) * DZ + col;
        float4 v = *(const float4*)(sC + row * 64 + tx * 4);
        float4 o;
        o.x = do_sp ? sp_beta(v.x, 1.2f, 1.f/1.2f) : fmaxf(v.x, 0.f);
        o.y = do_sp ? sp_beta(v.y, 1.2f, 1.f/1.2f) : fmaxf(v.y, 0.f);
        o.z = do_sp ? sp_beta(v.z, 1.2f, 1.f/1.2f) : fmaxf(v.z, 0.f);
        o.w = do_sp ? sp_beta(v.w, 1.2f, 1.f/1.2f) : fmaxf(v.w, 0.f);
        *(float4*)(Cd + gbase) = o;
        if (do_sp)   // fp16 sigma_p, tiled, for theta GEMM
            cvt4(o, g_sp, act_idx(by * 128 + row, col, DZ));
    }
}

// ---------------- back GEMMs: MODE 3 = r1 emit, 4 = rec2, 5 = theta ----------
// BMT = 128 (256 thr, 4 CTA/SM) or 64 (128 thr, more CTAs for chip fill)
template<int MODE, int BMT>
__global__ __launch_bounds__(BMT * 2, (BMT == 128) ? 4 : 6)
void tc_gemm(const half* __restrict__ A0h, int K0,
             const half* __restrict__ B0h,
             float* __restrict__ C0, const float* __restrict__ aux0,
             const float* __restrict__ aux1, half* __restrict__ Chi)
{
    extern __shared__ __align__(16) char smem[];
    __shared__ __align__(8) uint64_t mbars[3];
    __shared__ float red[256];

    const int tid = threadIdx.x;
    const int wid = tid >> 5;
    const int bx = blockIdx.x, by = blockIdx.y;
    const int wm = wid >> 1, wn = wid & 1;
    const int nc = K0 / 32;
    const uint32_t smb = smem_u32(smem);
    const uint32_t mbb = smem_u32(mbars);
    const int rowbase = by * BMT;

    if (tid == 0)
        for (int s = 0; s < 3; ++s) mbar_init(mbb + s * 8, 1);
    __syncthreads();

    auto issue = [&](int c) {
        if (tid != 0) return;
        int s = c % 3;
        uint32_t mb = mbb + s * 8;
        uint32_t dst = smb + s * STAGEB(BMT);
        mbar_expect(mb, STAGEB(BMT));
        const half* asrc = A0h + ((size_t)((rowbase >> 7) * (K0 >> 5) + c)) * 5120
                                + (size_t)(rowbase & 127) * 40;
        bulk_g2s(dst, asrc, BMT * 80, mb);
        bulk_g2s(dst + OFF_B(BMT), B0h + ((size_t)(bx * (K0 >> 5) + c)) * 2560, 5120, mb);
    };

    wmma::fragment<wmma::accumulator, 16, 16, 16, float> acc[2][2];
#pragma unroll
    for (int tm = 0; tm < 2; ++tm)
#pragma unroll
        for (int tn = 0; tn < 2; ++tn)
            wmma::fill_fragment(acc[tm][tn], 0.f);

    issue(0);
    if (nc > 1) issue(1);
    for (int c = 0; c < nc; ++c) {
        mbar_wait(mbb + (c % 3) * 8, (uint32_t)((c / 3) & 1));
        __syncthreads();
        if (c + 2 < nc) issue(c + 2);
        const half* sAh = (const half*)(smem + (c % 3) * STAGEB(BMT));
        const half* sBh = (const half*)(smem + (c % 3) * STAGEB(BMT) + OFF_B(BMT));
        GEMM_COMPUTE_CHUNK(sAh, sBh)
    }

    __syncthreads();
    float* sC = (float*)smem;
#pragma unroll
    for (int tm = 0; tm < 2; ++tm)
#pragma unroll
        for (int tn = 0; tn < 2; ++tn)
            wmma::store_matrix_sync(sC + (wm * 32 + tm * 16) * 64 + wn * 32 + tn * 16,
                                    acc[tm][tn], 64, wmma::mem_row_major);
    __syncthreads();

    if (MODE == 5) {   // theta finalize (cols 0..15 only)
        int row = tid >> 1, c0 = (tid & 1) * 8;
        size_t gb = (size_t)(rowbase + row) * DT + c0;
#pragma unroll
        for (int j = 0; j < 8; ++j) {
            float dot = sC[row * 64 + c0 + j];
            float th_h = 0.5f * aux0[gb + j] + 0.1f * aux1[gb + j] - dot;
            float u = 0.5f * th_h;
            C0[gb + j] = 0.001f * ((u > 20.f) ? th_h : 2.0f * log1pf(expf(u)));
        }
        return;
    }

    float lsum = 0.f;
    const int tx = tid & 15, ty = tid >> 4;
    const int N = (MODE == 4) ? 1024 : 256;
    const int col0 = bx * 64;
#pragma unroll
    for (int i = 0; i < 8; ++i) {
        int row = ty * 8 + i;
        int col = col0 + tx * 4;
        size_t gbase = (size_t)(rowbase + row) * N + col;
        float4 v = *(const float4*)(sC + row * 64 + tx * 4);
        if (MODE == 3) {
            cvt4(v, Chi, act_idx(rowbase + row, col, DREC));   // r1 fp16 tiled
        } else {
            float4 a0 = *(const float4*)(aux0 + gbase);
            float4 o;
            o.x = 1.f / (1.f + expf(-v.x)); { float d = a0.x - o.x; lsum += d * d; }
            o.y = 1.f / (1.f + expf(-v.y)); { float d = a0.y - o.y; lsum += d * d; }
            o.z = 1.f / (1.f + expf(-v.z)); { float d = a0.z - o.z; lsum += d * d; }
            o.w = 1.f / (1.f + expf(-v.w)); { float d = a0.w - o.w; lsum += d * d; }
            *(float4*)(C0 + gbase) = o;
        }
    }

    if (MODE == 4) {
        red[tid] = lsum;
        __syncthreads();
#pragma unroll
        for (int s = BMT; s > 0; s >>= 1) {
            if (tid < s) red[tid] += red[tid + s];
            __syncthreads();
        }
        if (tid == 0) atomicAdd(&g_acc[0], (double)red[0]);
    }
}

// ---------------- z elementwise: thresholds, z, z_hat, losses ----------------
__global__ __launch_bounds__(256)
void z_elem(const float* __restrict__ W_t2z,
            const float* __restrict__ eps_z,
            const float* __restrict__ eps_zhat,
            float* __restrict__ z_out,
            float* __restrict__ zhat_out)
{
    __shared__ float sWt[DT][DZ + 4];
    __shared__ float sTh[4][DT];
    __shared__ float red[256];

    const int tid = threadIdx.x;
    const int row0 = blockIdx.x * 4;

    for (int idx = tid; idx < DZ * DT; idx += 256) {
        int n = idx >> 4, t = idx & 15;
        sWt[t][n] = fmaxf(W_t2z[idx], 0.f);
    }
    if (tid < 64)
        sTh[tid >> 4][tid & 15] = g_theta[(size_t)row0 * DT + tid];
    __syncthreads();

    const int r = tid >> 6;
    const int q = tid & 63;
    const int row = row0 + r;
    const size_t idx = (size_t)row * DZ + q * 4;

    float4 muq = *(const float4*)(g_mu_q + idx);
    float4 sgq = *(const float4*)(g_sigma_q + idx);
    float4 epz = *(const float4*)(eps_z + idx);
    float4 eph = *(const float4*)(eps_zhat + idx);
    float4 mup = *(const float4*)(g_mu_p + idx);
    float4 sp4 = *(const float4*)(g_sigma_p + idx);

    float4 thr = make_float4(0.f, 0.f, 0.f, 0.f);
#pragma unroll
    for (int t = 0; t < DT; ++t) {
        float th = sTh[r][t];
        float4 w = *(const float4*)(&sWt[t][q * 4]);
        thr.x = fmaf(th, w.x, thr.x);
        thr.y = fmaf(th, w.y, thr.y);
        thr.z = fmaf(th, w.z, thr.z);
        thr.w = fmaf(th, w.w, thr.w);
    }

    float4 zv, zh;
    float raw;
    raw = fminf(fmaxf(fmaf(epz.x, sgq.x, muq.x), 0.f), 1.f);
    zv.x = fmaxf(raw - 10.f * thr.x, 0.f);  zh.x = fmaf(eph.x, sp4.x, mup.x);
    raw = fminf(fmaxf(fmaf(epz.y, sgq.y, muq.y), 0.f), 1.f);
    zv.y = fmaxf(raw - 10.f * thr.y, 0.f);  zh.y = fmaf(eph.y, sp4.y, mup.y);
    raw = fminf(fmaxf(fmaf(epz.z, sgq.z, muq.z), 0.f), 1.f);
    zv.z = fmaxf(raw - 10.f * thr.z, 0.f);  zh.z = fmaf(eph.z, sp4.z, mup.z);
    raw = fminf(fmaxf(fmaf(epz.w, sgq.w, muq.w), 0.f), 1.f);
    zv.w = fmaxf(raw - 10.f * thr.w, 0.f);  zh.w = fmaf(eph.w, sp4.w, mup.w);

    *(float4*)(z_out + idx) = zv;
    *(float4*)(zhat_out + idx) = zh;
    cvt4(zv, g_z, act_idx(row, q * 4, DZ));

    float e_sum = zv.x + zv.y + zv.z + zv.w;
    float t_sum = 0.f, d;
    d = zv.x - zh.x; t_sum = fmaf(d, d, t_sum);
    d = zv.y - zh.y; t_sum = fmaf(d, d, t_sum);
    d = zv.z - zh.z; t_sum = fmaf(d, d, t_sum);
    d = zv.w - zh.w; t_sum = fmaf(d, d, t_sum);

    red[tid] = e_sum; __syncthreads();
#pragma unroll
    for (int s = 128; s > 0; s >>= 1) { if (tid < s) red[tid] += red[tid + s]; __syncthreads(); }
    if (tid == 0) atomicAdd(&g_acc[2], (double)red[0]);
    __syncthreads();
    red[tid] = t_sum; __syncthreads();
#pragma unroll
    for (int s = 128; s > 0; s >>= 1) { if (tid < s) red[tid] += red[tid + s]; __syncthreads(); }
    if (tid == 0) atomicAdd(&g_acc[1], (double)red[0]);
}

// ---------------- finalize ----------------------------------------------------
__global__ void finalize_kernel(float* __restrict__ out_scalars) {
    if (threadIdx.x == 0) {
        out_scalars[0] = (float)(g_acc[0] / (double)((size_t)BATCH * DIN));
        out_scalars[1] = (float)(g_acc[1] / (double)((size_t)BATCH * DZ));
        out_scalars[2] = (float)(g_acc[2] / (double)((size_t)BATCH * DZ));
    }
}

// ---------------- launch -----------------------------------------------------
extern "C" void kernel_launch(void* const* d_in, const int* in_sizes, int n_in,
                              void* d_out, int out_size)
{
    const float* I_t        = (const float*)d_in[0];
    const float* h_m_1      = (const float*)d_in[1];
    const float* z_m_1      = (const float*)d_in[2];
    const float* theta_m_1  = (const float*)d_in[3];
    const float* eps_z      = (const float*)d_in[4];
    const float* eps_zhat   = (const float*)d_in[5];
    const float* W_post_mu  = (const float*)d_in[6];
    const float* W_post_lv  = (const float*)d_in[7];
    const float* W_z2h      = (const float*)d_in[8];
    const float* W_h2h      = (const float*)d_in[9];
    const float* W_prior_mu = (const float*)d_in[10];
    const float* W_prior_lv = (const float*)d_in[11];
    const float* W_i2t      = (const float*)d_in[12];
    const float* W_vip2t    = (const float*)d_in[13];
    const float* W_t2z      = (const float*)d_in[14];
    const float* W_rec1     = (const float*)d_in[15];
    const float* W_rec2     = (const float*)d_in[16];

    float* out       = (float*)d_out;
    float* out_ihat  = out;
    float* out_z     = out + (size_t)BATCH * DIN;
    float* out_h     = out_z + (size_t)BATCH * DZ;
    float* out_zhat  = out_h + (size_t)BATCH * DH;
    float* out_scal  = out_zhat + (size_t)BATCH * DZ;

    float *mu_q, *sigma_q, *sigma_p, *mu_p, *ti, *theta;
    cudaGetSymbolAddress((void**)&mu_q,    g_mu_q);
    cudaGetSymbolAddress((void**)&sigma_q, g_sigma_q);
    cudaGetSymbolAddress((void**)&sigma_p, g_sigma_p);
    cudaGetSymbolAddress((void**)&mu_p,    g_mu_p);
    cudaGetSymbolAddress((void**)&ti,      g_ti);
    cudaGetSymbolAddress((void**)&theta,   g_theta);
    half *z_t, *sp_t, *r1_t, *Wv_t, *Wr1_t, *Wr2_t;
    cudaGetSymbolAddress((void**)&z_t,  g_z);
    cudaGetSymbolAddress((void**)&sp_t, g_sp);
    cudaGetSymbolAddress((void**)&r1_t, g_r1);
    cudaGetSymbolAddress((void**)&Wv_t, g_Wv);
    cudaGetSymbolAddress((void**)&Wr1_t, g_Wr1w);
    cudaGetSymbolAddress((void**)&Wr2_t, g_Wr2w);

    const int SM128 = 3 * STAGEB(128);   // 46080
    const int SM64  = 3 * STAGEB(64);    // 30720
    cudaFuncSetAttribute(gemm_front, cudaFuncAttributeMaxDynamicSharedMemorySize, SM128);
    cudaFuncSetAttribute(tc_gemm<3, 64>,  cudaFuncAttributeMaxDynamicSharedMemorySize, SM64);
    cudaFuncSetAttribute(tc_gemm<4, 128>, cudaFuncAttributeMaxDynamicSharedMemorySize, SM128);
    cudaFuncSetAttribute(tc_gemm<5, 64>,  cudaFuncAttributeMaxDynamicSharedMemorySize, SM64);

    const dim3 blk(256);
    const dim3 blk64(128);

    cvt_all<<<(CVT_TOTAL + 1023) / 1024, blk>>>(
        (const float4*)I_t, (const float4*)h_m_1, (const float4*)z_m_1,
        (const float4*)W_post_mu, (const float4*)W_post_lv,
        (const float4*)W_z2h, (const float4*)W_h2h,
        (const float4*)W_prior_mu, (const float4*)W_prior_lv,
        (const float4*)W_i2t, (const float4*)W_rec1, (const float4*)W_rec2,
        (const float4*)W_vip2t);

    gemm_front<<<dim3(21, BATCH / 128), blk, SM128>>>(
        mu_q, sigma_q, ti, mu_p, sigma_p, out_h);

    // theta = 0.001*softplus_0.5(0.5*theta_m_1 + 0.1*ti - sigma_p @ relu(Wv)^T)
    tc_gemm<5, 64><<<dim3(1, BATCH / 64), blk64, SM64>>>(
        sp_t, DZ, Wv_t, theta, theta_m_1, ti, nullptr);

    z_elem<<<BATCH / 4, blk>>>(W_t2z, eps_z, eps_zhat, out_z, out_zhat);

    tc_gemm<3, 64><<<dim3(4, BATCH / 64), blk64, SM64>>>(
        z_t, DZ, Wr1_t, nullptr, nullptr, nullptr, r1_t);

    tc_gemm<4, 128><<<dim3(16, BATCH / 128), blk, SM128>>>(
        r1_t, DREC, Wr2_t, out_ihat, I_t, nullptr, nullptr);

    finalize_kernel<<<1, 32>>>(out_scal);
    (void)in_sizes; (void)n_in; (void)out_size;
}